// round 1
// baseline (speedup 1.0000x reference)
#include <cuda_runtime.h>
#include <math.h>

#define B    32
#define NIN  512
#define DIN  64
#define NOUT 32
#define DOUT 64
#define MD   (NOUT*DOUT)   // 2048

// d_out layout (fp32, tuple concat order):
//   next_capsule_value [32,32,64]      @ 0       (65536)
//   next_act           [32,32]         @ 65536   (1024)
//   query_key          [32,512,32]     @ 66560   (524288)
//   route_class_emb    [32,512,32,64]  @ 590848  (33554432)
#define OFF_CAP 0
#define OFF_ACT 65536
#define OFF_QK  66560
#define OFF_EMB 590848

// Ping-pong capsule state scratch (static __device__ — no allocation)
__device__ float g_cap[2][B * MD];

// ---------------------------------------------------------------------------
// Kernel 1: votes[b,n,m,d] = sum_a pose[b,n,a] * W[n,a,m,d]
// grid (512 n, 4 md-tiles of 512), 128 threads; each thread owns 4 md (float4)
// ---------------------------------------------------------------------------
__global__ __launch_bounds__(128) void votes_kernel(
    const float* __restrict__ pose, const float* __restrict__ W,
    float* __restrict__ votes)
{
    int n   = blockIdx.x;
    int tid = threadIdx.x;
    int md  = blockIdx.y * 512 + tid * 4;

    __shared__ float pose_s[B][DIN];
    for (int i = tid; i < B * DIN; i += 128) {
        int b = i >> 6, a = i & 63;
        pose_s[b][a] = pose[(b * NIN + n) * DIN + a];
    }
    __syncthreads();

    const float* Wn = W + (size_t)n * DIN * MD + md;

    for (int bc = 0; bc < 4; ++bc) {
        float4 acc[8];
        #pragma unroll
        for (int j = 0; j < 8; ++j) acc[j] = make_float4(0.f, 0.f, 0.f, 0.f);

        #pragma unroll 4
        for (int a = 0; a < DIN; ++a) {
            float4 w = *(const float4*)(Wn + (size_t)a * MD);
            #pragma unroll
            for (int j = 0; j < 8; ++j) {
                float p = pose_s[bc * 8 + j][a];
                acc[j].x += p * w.x; acc[j].y += p * w.y;
                acc[j].z += p * w.z; acc[j].w += p * w.w;
            }
        }
        #pragma unroll
        for (int j = 0; j < 8; ++j) {
            int b = bc * 8 + j;
            *(float4*)(votes + ((size_t)b * NIN + n) * MD + md) = acc[j];
        }
    }
}

// ---------------------------------------------------------------------------
// Kernel 2: cap0[b,md] = sum_n votes[b,n,md] / NOUT
// grid (8, 32), 256 threads
// ---------------------------------------------------------------------------
__global__ __launch_bounds__(256) void cap0_kernel(
    const float* __restrict__ votes, float* __restrict__ cap)
{
    int b  = blockIdx.y;
    int md = blockIdx.x * 256 + threadIdx.x;
    const float* v = votes + (size_t)b * NIN * MD + md;
    float s = 0.f;
    #pragma unroll 8
    for (int n = 0; n < NIN; ++n) s += v[(size_t)n * MD];
    cap[b * MD + md] = s * (1.0f / NOUT);
}

// ---------------------------------------------------------------------------
// Kernel 3: one routing iteration.
// grid (16 n-chunks of 32, 32 b), 256 threads: tid = m*8 + j, j covers 8 d's.
// Reads cap_in, accumulates cap_out (must be zeroed), on final iteration also
// writes query_key and route_class_emb (in place over votes).
// ---------------------------------------------------------------------------
__global__ __launch_bounds__(256) void route_kernel(
    float* __restrict__ votes, const float* __restrict__ act,
    const float* __restrict__ cap_in, float* __restrict__ cap_out,
    float* __restrict__ qk_out, int final_flag)
{
    int b   = blockIdx.y;
    int n0  = blockIdx.x * 32;
    int tid = threadIdx.x;
    int m   = tid >> 3;
    int j   = tid & 7;

    // preload this thread's slice of current capsule pose
    float capr[8];
    #pragma unroll
    for (int k = 0; k < 8; ++k)
        capr[k] = cap_in[(b * NOUT + m) * DOUT + j * 8 + k];

    __shared__ float lg[NOUT];
    __shared__ float qk_s[NOUT];

    float acc[8];
    #pragma unroll
    for (int k = 0; k < 8; ++k) acc[k] = 0.f;

    for (int nn = 0; nn < 32; ++nn) {
        int n = n0 + nn;
        float* vp = votes + ((size_t)b * NIN + n) * MD + m * DOUT + j * 8;
        float4 v0 = *(const float4*)vp;
        float4 v1 = *(const float4*)(vp + 4);

        // logits: dot(votes[b,n,m,:], cap[b,m,:]) * scale
        float part = v0.x * capr[0] + v0.y * capr[1] + v0.z * capr[2] + v0.w * capr[3]
                   + v1.x * capr[4] + v1.y * capr[5] + v1.z * capr[6] + v1.w * capr[7];
        part += __shfl_xor_sync(0xffffffffu, part, 1);
        part += __shfl_xor_sync(0xffffffffu, part, 2);
        part += __shfl_xor_sync(0xffffffffu, part, 4);
        if (j == 0) lg[m] = part * 0.125f;   // 1/sqrt(64)
        __syncthreads();

        // softmax over m (warp 0)
        if (tid < 32) {
            float x = lg[tid];
            float mx = x;
            #pragma unroll
            for (int o = 16; o; o >>= 1)
                mx = fmaxf(mx, __shfl_xor_sync(0xffffffffu, mx, o));
            float e = __expf(x - mx);
            float s = e;
            #pragma unroll
            for (int o = 16; o; o >>= 1)
                s += __shfl_xor_sync(0xffffffffu, s, o);
            qk_s[tid] = e / s;
        }
        __syncthreads();

        float q  = qk_s[m];
        float wa = q * act[b * NIN + n];

        acc[0] += wa * v0.x; acc[1] += wa * v0.y;
        acc[2] += wa * v0.z; acc[3] += wa * v0.w;
        acc[4] += wa * v1.x; acc[5] += wa * v1.y;
        acc[6] += wa * v1.z; acc[7] += wa * v1.w;

        if (final_flag) {
            float4 e0 = make_float4(wa * v0.x, wa * v0.y, wa * v0.z, wa * v0.w);
            float4 e1 = make_float4(wa * v1.x, wa * v1.y, wa * v1.z, wa * v1.w);
            *(float4*)vp       = e0;   // route_class_emb overwrites votes in place
            *(float4*)(vp + 4) = e1;
            if (j == 0) qk_out[((size_t)b * NIN + n) * NOUT + m] = q;
        }
    }

    int base = (b * NOUT + m) * DOUT + j * 8;
    #pragma unroll
    for (int k = 0; k < 8; ++k) atomicAdd(&cap_out[base + k], acc[k]);
}

// ---------------------------------------------------------------------------
// Kernel 4: next_act[b,m] = ||cap[b,m,:]||_2
// ---------------------------------------------------------------------------
__global__ void act_kernel(const float* __restrict__ cap, float* __restrict__ actout)
{
    int i = blockIdx.x * blockDim.x + threadIdx.x;   // 0..1023
    if (i < B * NOUT) {
        const float* c = cap + i * DOUT;
        float s = 0.f;
        #pragma unroll
        for (int d = 0; d < DOUT; ++d) s += c[d] * c[d];
        actout[i] = sqrtf(s);
    }
}

__global__ void zero_kernel(float* __restrict__ p, int n)
{
    int i = blockIdx.x * blockDim.x + threadIdx.x;
    if (i < n) p[i] = 0.f;
}

// ---------------------------------------------------------------------------
extern "C" void kernel_launch(void* const* d_in, const int* in_sizes, int n_in,
                              void* d_out, int out_size)
{
    const float* pose = (const float*)d_in[0];
    const float* act  = (const float*)d_in[1];
    const float* W    = (const float*)d_in[2];
    // d_in[3] = num_iter (always 3 in this dataset; loop unrolled below)

    float* out  = (float*)d_out;
    float* cap  = out + OFF_CAP;
    float* qk   = out + OFF_QK;
    float* emb  = out + OFF_EMB;   // doubles as the votes buffer

    float* capbuf;
    cudaGetSymbolAddress((void**)&capbuf, g_cap);
    float* cap0 = capbuf;
    float* cap1 = capbuf + B * MD;

    // 1) votes -> emb region
    votes_kernel<<<dim3(NIN, 4), 128>>>(pose, W, emb);

    // 2) initial capsule value = mean of votes over n
    cap0_kernel<<<dim3(8, B), 256>>>(emb, cap0);

    // 3) three routing iterations (ping-pong), last one writes qk + emb
    zero_kernel<<<(B * MD + 255) / 256, 256>>>(cap1, B * MD);
    route_kernel<<<dim3(16, B), 256>>>(emb, act, cap0, cap1, qk, 0);

    zero_kernel<<<(B * MD + 255) / 256, 256>>>(cap0, B * MD);
    route_kernel<<<dim3(16, B), 256>>>(emb, act, cap1, cap0, qk, 0);

    zero_kernel<<<(B * MD + 255) / 256, 256>>>(cap, B * MD);
    route_kernel<<<dim3(16, B), 256>>>(emb, act, cap0, cap, qk, 1);

    // 4) next_act = L2 norm of final capsule poses
    act_kernel<<<4, 256>>>(cap, out + OFF_ACT);
}